// round 1
// baseline (speedup 1.0000x reference)
#include <cuda_runtime.h>

// u: [16384, 2, 2048] float32 -> out: [16384, 2, 2048] float32
// du = 6th-order central diff along l (interior [10, 2038)), zero in ghosts.
// out[:,0,:] = -(u1*du0 + u0*du1)
// out[:,1,:] = -(2*du0 + u1*du1)

#define L 2048
#define IGST 10
#define ROW 4096  // 2 channels * L

__global__ __launch_bounds__(256) void centdif_kernel(const float* __restrict__ u,
                                                      float* __restrict__ out) {
    __shared__ float s[ROW];  // s[0..2047] = channel 0, s[2048..4095] = channel 1

    const int tid = threadIdx.x;
    const long base = (long)blockIdx.x * ROW;

    // Vectorized cooperative load of the whole row (both channels): 4096 floats = 1024 float4
    const float4* __restrict__ up = (const float4*)(u + base);
    float4* sp = (float4*)s;
#pragma unroll
    for (int i = 0; i < 4; i++) {
        sp[tid + i * 256] = up[tid + i * 256];
    }
    __syncthreads();

    const float c = 1.0f / (60.0f * 0.012f);

#pragma unroll
    for (int i = 0; i < 8; i++) {
        const int l = tid + i * 256;
        float du0 = 0.0f, du1 = 0.0f;
        if (l >= IGST && l < L - IGST) {
            du0 = (-s[l - 3] + 9.0f * s[l - 2] - 45.0f * s[l - 1]
                   + 45.0f * s[l + 1] - 9.0f * s[l + 2] + s[l + 3]) * c;
            du1 = (-s[L + l - 3] + 9.0f * s[L + l - 2] - 45.0f * s[L + l - 1]
                   + 45.0f * s[L + l + 1] - 9.0f * s[L + l + 2] + s[L + l + 3]) * c;
        }
        const float u0 = s[l];
        const float u1 = s[L + l];
        out[base + l]     = -(u1 * du0 + u0 * du1);
        out[base + L + l] = -(2.0f * du0 + u1 * du1);
    }
}

extern "C" void kernel_launch(void* const* d_in, const int* in_sizes, int n_in,
                              void* d_out, int out_size) {
    const float* u = (const float*)d_in[0];
    float* out = (float*)d_out;
    const int m = in_sizes[0] / ROW;  // 16384
    centdif_kernel<<<m, 256>>>(u, out);
}

// round 2
// speedup vs baseline: 1.0999x; 1.0999x over previous
#include <cuda_runtime.h>

// u: [16384, 2, 2048] float32 -> out: [16384, 2, 2048] float32
// du = 6th-order central diff along l (interior [10, 2038)), zero in ghosts.
// out[:,0,:] = -(u1*du0 + u0*du1)
// out[:,1,:] = -(2*du0 + u1*du1)

#define L 2048
#define IGST 10
#define ROW 4096           // 2 channels * L
#define S_F4 1028          // 4112 floats: [1 f4 pad][512 f4 ch0][2 f4 pad][512 f4 ch1][1 f4 pad]
#define CH0_F4 1           // ch0 float4 base index in smem
#define CH1_F4 515         // ch1 float4 base index in smem

__global__ __launch_bounds__(256) void centdif_kernel(const float* __restrict__ u,
                                                      float* __restrict__ out) {
    __shared__ float4 s4[S_F4];

    const int tid = threadIdx.x;
    const long base = (long)blockIdx.x * ROW;

    // Cooperative vector load of the row: 1024 float4 (ch0 first 512, ch1 next 512)
    const float4* __restrict__ up = (const float4*)(u + base);
#pragma unroll
    for (int i = 0; i < 4; i++) {
        const int idx = tid + i * 256;
        s4[idx < 512 ? (idx + CH0_F4) : (idx - 512 + CH1_F4)] = up[idx];
    }
    __syncthreads();

    const float c = 1.0f / (60.0f * 0.012f);
    float4* __restrict__ op = (float4*)(out + base);

#pragma unroll
    for (int i = 0; i < 2; i++) {
        const int ck = tid + i * 256;     // chunk 0..511, covers l0 = 4*ck .. 4*ck+3
        const int l0 = 4 * ck;

        // window w[j] = s[l0-4+j], j=0..11 for each channel (3 LDS.128 each)
        const float4 A0 = s4[ck + CH0_F4 - 1];
        const float4 B0 = s4[ck + CH0_F4];
        const float4 C0 = s4[ck + CH0_F4 + 1];
        const float4 A1 = s4[ck + CH1_F4 - 1];
        const float4 B1 = s4[ck + CH1_F4];
        const float4 C1 = s4[ck + CH1_F4 + 1];

        const float w0[12] = {A0.x, A0.y, A0.z, A0.w, B0.x, B0.y, B0.z, B0.w, C0.x, C0.y, C0.z, C0.w};
        const float w1[12] = {A1.x, A1.y, A1.z, A1.w, B1.x, B1.y, B1.z, B1.w, C1.x, C1.y, C1.z, C1.w};

        float o0[4], o1[4];
#pragma unroll
        for (int k = 0; k < 4; k++) {
            const int p = l0 + k;
            const bool in = (p >= IGST) && (p < L - IGST);
            float du0 = (-w0[k + 1] + 9.0f * w0[k + 2] - 45.0f * w0[k + 3]
                         + 45.0f * w0[k + 5] - 9.0f * w0[k + 6] + w0[k + 7]) * c;
            float du1 = (-w1[k + 1] + 9.0f * w1[k + 2] - 45.0f * w1[k + 3]
                         + 45.0f * w1[k + 5] - 9.0f * w1[k + 6] + w1[k + 7]) * c;
            du0 = in ? du0 : 0.0f;
            du1 = in ? du1 : 0.0f;
            const float u0 = w0[k + 4];
            const float u1 = w1[k + 4];
            o0[k] = -(u1 * du0 + u0 * du1);
            o1[k] = -(2.0f * du0 + u1 * du1);
        }

        op[ck]       = make_float4(o0[0], o0[1], o0[2], o0[3]);
        op[512 + ck] = make_float4(o1[0], o1[1], o1[2], o1[3]);
    }
}

extern "C" void kernel_launch(void* const* d_in, const int* in_sizes, int n_in,
                              void* d_out, int out_size) {
    const float* u = (const float*)d_in[0];
    float* out = (float*)d_out;
    const int m = in_sizes[0] / ROW;  // 16384
    centdif_kernel<<<m, 256>>>(u, out);
}